// round 9
// baseline (speedup 1.0000x reference)
#include <cuda_runtime.h>

#define B_TOTAL   1024
#define T_STEPS   512
#define NGATE     256
#define NB        8
#define NCTA      128
#define NTHREADS  256

typedef unsigned long long u64;

__device__ __forceinline__ u64 ffma2(u64 a, u64 b, u64 c) {
    u64 d;
    asm("fma.rn.f32x2 %0, %1, %2, %3;" : "=l"(d) : "l"(a), "l"(b), "l"(c));
    return d;
}
__device__ __forceinline__ float hadd2(u64 v) {
    float lo, hi;
    asm("mov.b64 {%0, %1}, %2;" : "=f"(lo), "=f"(hi) : "l"(v));
    return lo + hi;
}
__device__ __forceinline__ float tanh_apx(float x) {
    float y;
    asm("tanh.approx.f32 %0, %1;" : "=f"(y) : "f"(x));
    return y;
}
__device__ __forceinline__ float sig_apx(float x) {
    return fmaf(0.5f, tanh_apx(0.5f * x), 0.5f);
}

// SMEM (bytes):
//  wqC  [0, 65536):      whh1 quads, layout [16 kc][256 g]   (conflict-free LDS.128)
//  g0   [65536,  73728): f32 [8 b][256 gate]
//  g1   [73728,  81920): f32 [8 b][256 gate]
//  h0   [81920,  83968): f32 [8 b][64 u]
//  h1   [83968,  86016): f32 [8 b][64 u]
//  wfc  [86016,  86272): f32 [64]
#define SM_WC     0
#define SM_G0     65536
#define SM_G1     73728
#define SM_H0     81920
#define SM_H1     83968
#define SM_WFC    86016
#define SMEM_BYTES 86272

__global__ void __launch_bounds__(NTHREADS, 1)
lstm2_kernel(const float* __restrict__ x,
             const float* __restrict__ W_ih0, const float* __restrict__ W_hh0,
             const float* __restrict__ b_ih0, const float* __restrict__ b_hh0,
             const float* __restrict__ W_ih1, const float* __restrict__ W_hh1,
             const float* __restrict__ b_ih1, const float* __restrict__ b_hh1,
             const float* __restrict__ W_fc,  const float* __restrict__ b_fc,
             float* __restrict__ out)
{
    extern __shared__ char smem[];
    ulonglong2* wqC = (ulonglong2*)(smem + SM_WC);
    float* g0_s  = (float*)(smem + SM_G0);
    float* g1_s  = (float*)(smem + SM_G1);
    float* h0_s  = (float*)(smem + SM_H0);
    float* h1_s  = (float*)(smem + SM_H1);
    float* wfc_s = (float*)(smem + SM_WFC);

    const int tid   = threadIdx.x;
    const int g     = tid;                 // gate row owned by this thread
    const int bbase = blockIdx.x * NB;

    // ---- register-resident weight rows: whh0 row g, wih1 row g (128 regs) ----
    u64 wA[32], wB[32];
    {
        const ulonglong2* pA = (const ulonglong2*)(W_hh0 + (size_t)g * 64);
        const ulonglong2* pB = (const ulonglong2*)(W_ih1 + (size_t)g * 64);
#pragma unroll
        for (int j = 0; j < 16; j++) {
            ulonglong2 vA = pA[j]; wA[2*j] = vA.x; wA[2*j+1] = vA.y;
            ulonglong2 vB = pB[j]; wB[2*j] = vB.x; wB[2*j+1] = vB.y;
        }
    }
    // ---- whh1 into SMEM quads [kc][g] ----
    for (int idx = tid; idx < 4096; idx += NTHREADS) {
        int row = idx >> 4, q = idx & 15;
        wqC[q * NGATE + row] = ((const ulonglong2*)W_hh1)[idx];
    }
    if (tid < 64) wfc_s[tid] = W_fc[tid];
    for (int i = tid; i < NB * 64; i += NTHREADS) { h0_s[i] = 0.0f; h1_s[i] = 0.0f; }

    const float b0v = b_ih0[g] + b_hh0[g];
    const float b1v = b_ih1[g] + b_hh1[g];

    // ---- act ownership: 4 units = (L0,b=q), (L0,b=q+4), (L1,b=q), (L1,b=q+4) ----
    const int u  = tid & 63;
    const int q  = tid >> 6;               // 0..3
    const int giA = q * NGATE + u;
    const int giB = (q + 4) * NGATE + u;
    const int hsA = q * 64 + u;
    const int hsB = (q + 4) * 64 + u;
    const float* xrA = x + (size_t)(bbase + q) * T_STEPS;
    const float* xrB = x + (size_t)(bbase + q + 4) * T_STEPS;
    const float wxi = W_ih0[u];
    const float wxf = W_ih0[64 + u];
    const float wxg = W_ih0[128 + u];
    const float wxo = W_ih0[192 + u];
    float c0A = 0.0f, c0B = 0.0f, c1A = 0.0f, c1B = 0.0f;

    auto actL0 = [&](int gi, int hs, float& c, float xv) {
        float q0 = fmaf(wxi, xv, g0_s[gi]);
        float q1 = fmaf(wxf, xv, g0_s[gi + 64]);
        float q2 = fmaf(wxg, xv, g0_s[gi + 128]);
        float q3 = fmaf(wxo, xv, g0_s[gi + 192]);
        float ii = sig_apx(q0), ff = sig_apx(q1), gv = tanh_apx(q2), oo = sig_apx(q3);
        c = ff * c + ii * gv;
        h0_s[hs] = oo * tanh_apx(c);
    };
    auto actL1 = [&](int gi, int hs, float& c) {
        float p0 = g1_s[gi];
        float p1 = g1_s[gi + 64];
        float p2 = g1_s[gi + 128];
        float p3 = g1_s[gi + 192];
        float ii = sig_apx(p0), ff = sig_apx(p1), gv = tanh_apx(p2), oo = sig_apx(p3);
        c = ff * c + ii * gv;
        h1_s[hs] = oo * tanh_apx(c);
    };

    __syncthreads();

    // ---- prologue: g0(0) = b0 ; act0(0) ----
#pragma unroll
    for (int b = 0; b < NB; b++) g0_s[b * NGATE + g] = b0v;
    __syncthreads();
    actL0(giA, hsA, c0A, __ldg(xrA));
    actL0(giB, hsB, c0B, __ldg(xrB));
    __syncthreads();

    // ======== main loop: mv = {g0(t+1), g1(t)}, act = {act1(t), act0(t+1)} ========
    for (int t = 0; t < T_STEPS - 1; t++) {
        u64 a0[NB], a1[NB];
#pragma unroll
        for (int b = 0; b < NB; b++) { a0[b] = 0ull; a1[b] = 0ull; }

        // whh0 . h0  and  wih1 . h0 (register weights, shared h0 broadcasts)
#pragma unroll
        for (int kc = 0; kc < 16; kc++) {
            u64 wa0 = wA[2*kc], wa1 = wA[2*kc+1];
            u64 wb0 = wB[2*kc], wb1 = wB[2*kc+1];
#pragma unroll
            for (int b = 0; b < NB; b++) {
                ulonglong2 h2 = *(const ulonglong2*)(h0_s + b * 64 + kc * 4);
                a0[b] = ffma2(wa0, h2.x, a0[b]); a0[b] = ffma2(wa1, h2.y, a0[b]);
                a1[b] = ffma2(wb0, h2.x, a1[b]); a1[b] = ffma2(wb1, h2.y, a1[b]);
            }
        }
        // store g0 early (frees a0, hides store latency)
#pragma unroll
        for (int b = 0; b < NB; b++)
            g0_s[b * NGATE + g] = hadd2(a0[b]) + b0v;

        // whh1 . h1 (SMEM weights, conflict-free)
#pragma unroll
        for (int kc = 0; kc < 16; kc++) {
            ulonglong2 wc = wqC[kc * NGATE + g];
#pragma unroll
            for (int b = 0; b < NB; b++) {
                ulonglong2 h2 = *(const ulonglong2*)(h1_s + b * 64 + kc * 4);
                a1[b] = ffma2(wc.x, h2.x, a1[b]); a1[b] = ffma2(wc.y, h2.y, a1[b]);
            }
        }
#pragma unroll
        for (int b = 0; b < NB; b++)
            g1_s[b * NGATE + g] = hadd2(a1[b]) + b1v;

        __syncthreads();   // mv -> act

        {
            float xvA = __ldg(xrA + t + 1);
            float xvB = __ldg(xrB + t + 1);
            actL1(giA, hsA, c1A);
            actL1(giB, hsB, c1B);
            actL0(giA, hsA, c0A, xvA);
            actL0(giB, hsB, c0B, xvB);
        }
        __syncthreads();   // act -> mv
    }

    // ======== epilogue: g1(511) ; act1(511) ========
    {
        u64 a1[NB];
#pragma unroll
        for (int b = 0; b < NB; b++) a1[b] = 0ull;
#pragma unroll
        for (int kc = 0; kc < 16; kc++) {
            u64 wb0 = wB[2*kc], wb1 = wB[2*kc+1];
#pragma unroll
            for (int b = 0; b < NB; b++) {
                ulonglong2 h2 = *(const ulonglong2*)(h0_s + b * 64 + kc * 4);
                a1[b] = ffma2(wb0, h2.x, a1[b]); a1[b] = ffma2(wb1, h2.y, a1[b]);
            }
        }
#pragma unroll
        for (int kc = 0; kc < 16; kc++) {
            ulonglong2 wc = wqC[kc * NGATE + g];
#pragma unroll
            for (int b = 0; b < NB; b++) {
                ulonglong2 h2 = *(const ulonglong2*)(h1_s + b * 64 + kc * 4);
                a1[b] = ffma2(wc.x, h2.x, a1[b]); a1[b] = ffma2(wc.y, h2.y, a1[b]);
            }
        }
#pragma unroll
        for (int b = 0; b < NB; b++)
            g1_s[b * NGATE + g] = hadd2(a1[b]) + b1v;
        __syncthreads();

        actL1(giA, hsA, c1A);
        actL1(giB, hsB, c1B);
    }
    __syncthreads();

    // ---- output FC ----
    if (tid < 16) {
        int b = tid & 7;
        const float* hp = (tid < 8) ? h0_s : h1_s;
        float s = b_fc[0];
#pragma unroll
        for (int uu = 0; uu < 64; uu++)
            s = fmaf(hp[b * 64 + uu], wfc_s[uu], s);
        out[(tid < 8 ? 0 : B_TOTAL) + bbase + b] = s;
    }
}

extern "C" void kernel_launch(void* const* d_in, const int* in_sizes, int n_in,
                              void* d_out, int out_size) {
    const float* x     = (const float*)d_in[0];
    const float* W_ih0 = (const float*)d_in[1];
    const float* W_hh0 = (const float*)d_in[2];
    const float* b_ih0 = (const float*)d_in[3];
    const float* b_hh0 = (const float*)d_in[4];
    const float* W_ih1 = (const float*)d_in[5];
    const float* W_hh1 = (const float*)d_in[6];
    const float* b_ih1 = (const float*)d_in[7];
    const float* b_hh1 = (const float*)d_in[8];
    const float* W_fc  = (const float*)d_in[9];
    const float* b_fc  = (const float*)d_in[10];
    float* out = (float*)d_out;

    cudaFuncSetAttribute(lstm2_kernel,
                         cudaFuncAttributeMaxDynamicSharedMemorySize, SMEM_BYTES);
    lstm2_kernel<<<NCTA, NTHREADS, SMEM_BYTES>>>(
        x, W_ih0, W_hh0, b_ih0, b_hh0,
        W_ih1, W_hh1, b_ih1, b_hh1, W_fc, b_fc, out);
}

// round 10
// speedup vs baseline: 1.1521x; 1.1521x over previous
#include <cuda_runtime.h>

#define B_TOTAL   1024
#define T_STEPS   512
#define NGATE     256
#define NCTA      148
#define NCTA7     136      /* 136 CTAs * 7 + 12 CTAs * 6 = 1024 */
#define NTHREADS  384
#define HSTRIDE   68

typedef unsigned long long u64;

__device__ __forceinline__ u64 ffma2(u64 a, u64 b, u64 c) {
    u64 d;
    asm("fma.rn.f32x2 %0, %1, %2, %3;" : "=l"(d) : "l"(a), "l"(b), "l"(c));
    return d;
}
__device__ __forceinline__ float hadd2(u64 v) {
    float lo, hi;
    asm("mov.b64 {%0, %1}, %2;" : "=f"(lo), "=f"(hi) : "l"(v));
    return lo + hi;
}
__device__ __forceinline__ float tanh_apx(float x) {
    float y;
    asm("tanh.approx.f32 %0, %1;" : "=f"(y) : "f"(x));
    return y;
}
__device__ __forceinline__ float sig_apx(float x) {
    return fmaf(0.5f, tanh_apx(0.5f * x), 0.5f);
}

// SMEM (bytes), arrays sized for NB=7:
//  wq   [0, 196608): quads. A=whh0 [0,4096), B=wih1 [4096,8192), C=whh1 [8192,12288)
//       A/B sublayout: [rowhi][kc][half][row&127]   conflict-free
//       C   sublayout: [row>>6][kc][half][row&63]   conflict-free
//  g0   [196608): f32 [7 b][256 g]
//  g1a  [203776): f32 [7 b][256 g]
//  g1b  [210944): f32 [7 b][256 g]
//  h0   [218112): f32 [7 b][68]   half0 @ +0, half1 @ +36 floats
//  h1   [220016)
//  wfc  [221920): f32 [64]
#define SM_W      0
#define SM_G0     196608
#define SM_G1A    203776
#define SM_G1B    210944
#define SM_H0     218112
#define SM_H1     220016
#define SM_WFC    221920
#define SMEM_BYTES 222176

template<int NBT>
__device__ __forceinline__ void lstm_body(
    int bbase, const float* __restrict__ x,
    const float* __restrict__ W_ih0,
    const float* __restrict__ b_ih0, const float* __restrict__ b_hh0,
    const float* __restrict__ b_ih1, const float* __restrict__ b_hh1,
    const float* __restrict__ b_fc, float* __restrict__ out,
    ulonglong2* wq, float* g0_s, float* g1a_s, float* g1b_s,
    float* h0_s, float* h1_s, float* wfc_s)
{
    const int tid  = threadIdx.x;
    const int lane = tid & 31;
    const int half = lane >> 4;
    const int hofs = half * 36;
    const int wid  = tid >> 5;

    for (int i = tid; i < NBT * HSTRIDE; i += NTHREADS) { h0_s[i] = 0.0f; h1_s[i] = 0.0f; }

    // ---- matvec roles (identical to round-8) ----
    const bool isA  = (tid < 256);
    const int sl    = (wid & 7) * 16 + (lane & 15);
    const int wofsA = half * 128 + sl;
    const int myrow = sl + half * 128;
    const int sb    = (wid - 8) * 16 + (lane & 15);
    const int wofsC = half * 64 + sb;
    const int rX    = sb + 64 * (half * 2);
    const int rY    = rX + 64;

    float b0v = 0.0f, b1v = 0.0f;
    if (isA) {
        b0v = b_ih0[myrow] + b_hh0[myrow];
        b1v = b_ih1[myrow] + b_hh1[myrow];
    }

    // ---- act ownership ----
    const int u = tid & 63;
    const float wxi = W_ih0[u];
    const float wxf = W_ih0[64 + u];
    const float wxg = W_ih0[128 + u];
    const float wxo = W_ih0[192 + u];
    const int pad = (u >> 5) << 2;

    // unit0: always L0, b0u = tid>>6 (0..5)
    const int b0u = tid >> 6;
    const int gi0 = b0u * NGATE + u;
    const int hs0 = b0u * HSTRIDE + u + pad;
    const float* xr0 = x + (size_t)(bbase + b0u) * T_STEPS;

    // NBT==7: unit1 = L0 b=6 (tid<64) | L1 b=(tid-64)>>6 ; unit2 (tid<128) = L1 b=(tid+320)>>6
    // NBT==6: unit1 = L1 b=tid>>6 ; no unit2
    const bool u1L0  = (NBT == 7) && (tid < 64);
    const bool hasU2 = (NBT == 7) && (tid < 128);
    const int b1u = (NBT == 7) ? (u1L0 ? 6 : ((tid - 64) >> 6)) : b0u;
    const int b2u = (NBT == 7) ? ((tid + 320) >> 6) : 0;
    const int gi1 = b1u * NGATE + u;
    const int hs1 = b1u * HSTRIDE + u + pad;
    const int gi2 = b2u * NGATE + u;
    const int hs2 = b2u * HSTRIDE + u + pad;
    const float* xr1 = x + (size_t)(bbase + 6) * T_STEPS;   // used only if u1L0

    float cu0 = 0.0f, cu1 = 0.0f, cu2 = 0.0f;

    auto actL0 = [&](int gi, int hs, float& c, float xv) {
        float q0 = fmaf(wxi, xv, g0_s[gi]);
        float q1 = fmaf(wxf, xv, g0_s[gi + 64]);
        float q2 = fmaf(wxg, xv, g0_s[gi + 128]);
        float q3 = fmaf(wxo, xv, g0_s[gi + 192]);
        float ii = sig_apx(q0), ff = sig_apx(q1), gv = tanh_apx(q2), oo = sig_apx(q3);
        c = ff * c + ii * gv;
        h0_s[hs] = oo * tanh_apx(c);
    };
    auto actL1 = [&](int gi, int hs, float& c) {
        float p0 = g1a_s[gi]       + g1b_s[gi];
        float p1 = g1a_s[gi + 64]  + g1b_s[gi + 64];
        float p2 = g1a_s[gi + 128] + g1b_s[gi + 128];
        float p3 = g1a_s[gi + 192] + g1b_s[gi + 192];
        float ii = sig_apx(p0), ff = sig_apx(p1), gv = tanh_apx(p2), oo = sig_apx(p3);
        c = ff * c + ii * gv;
        h1_s[hs] = oo * tanh_apx(c);
    };

    __syncthreads();   // covers weight upload + h zero

    // ---- prologue: g0(0) = b0 ; act0(0) ----
    if (isA) {
#pragma unroll
        for (int b = 0; b < NBT; b++) g0_s[b * NGATE + myrow] = b0v;
    }
    __syncthreads();
    actL0(gi0, hs0, cu0, __ldg(xr0));
    if (u1L0) actL0(gi1, hs1, cu1, __ldg(xr1));
    __syncthreads();

    // ======== main loop ========
    for (int t = 0; t < T_STEPS - 1; t++) {
        if (isA) {
            u64 aA0[NBT], aA1[NBT], aB0[NBT], aB1[NBT];
#pragma unroll
            for (int b = 0; b < NBT; b++) { aA0[b]=0ull; aA1[b]=0ull; aB0[b]=0ull; aB1[b]=0ull; }
#pragma unroll
            for (int kc = 0; kc < 8; kc++) {
                ulonglong2 wa0 = wq[       kc * 256 + wofsA];
                ulonglong2 wa1 = wq[2048 + kc * 256 + wofsA];
                ulonglong2 wb0 = wq[4096 + kc * 256 + wofsA];
                ulonglong2 wb1 = wq[6144 + kc * 256 + wofsA];
#pragma unroll
                for (int b = 0; b < NBT; b++) {
                    ulonglong2 h2 = *(const ulonglong2*)(h0_s + b * HSTRIDE + hofs + kc * 4);
                    aA0[b] = ffma2(wa0.x, h2.x, aA0[b]); aA0[b] = ffma2(wa0.y, h2.y, aA0[b]);
                    aA1[b] = ffma2(wa1.x, h2.x, aA1[b]); aA1[b] = ffma2(wa1.y, h2.y, aA1[b]);
                    aB0[b] = ffma2(wb0.x, h2.x, aB0[b]); aB0[b] = ffma2(wb0.y, h2.y, aB0[b]);
                    aB1[b] = ffma2(wb1.x, h2.x, aB1[b]); aB1[b] = ffma2(wb1.y, h2.y, aB1[b]);
                }
            }
#pragma unroll
            for (int b = 0; b < NBT; b++) {
                float sA0 = hadd2(aA0[b]); sA0 += __shfl_xor_sync(0xffffffffu, sA0, 16);
                float sA1 = hadd2(aA1[b]); sA1 += __shfl_xor_sync(0xffffffffu, sA1, 16);
                float sB0 = hadd2(aB0[b]); sB0 += __shfl_xor_sync(0xffffffffu, sB0, 16);
                float sB1 = hadd2(aB1[b]); sB1 += __shfl_xor_sync(0xffffffffu, sB1, 16);
                g0_s [b * NGATE + myrow] = (half ? sA1 : sA0) + b0v;
                g1a_s[b * NGATE + myrow] = (half ? sB1 : sB0) + b1v;
            }
        } else {
            u64 aC0[NBT], aC1[NBT], aC2[NBT], aC3[NBT];
#pragma unroll
            for (int b = 0; b < NBT; b++) { aC0[b]=0ull; aC1[b]=0ull; aC2[b]=0ull; aC3[b]=0ull; }
#pragma unroll
            for (int kc = 0; kc < 8; kc++) {
                ulonglong2 wc0 = wq[8192        + kc * 128 + wofsC];
                ulonglong2 wc1 = wq[8192 + 1024 + kc * 128 + wofsC];
                ulonglong2 wc2 = wq[8192 + 2048 + kc * 128 + wofsC];
                ulonglong2 wc3 = wq[8192 + 3072 + kc * 128 + wofsC];
#pragma unroll
                for (int b = 0; b < NBT; b++) {
                    ulonglong2 h2 = *(const ulonglong2*)(h1_s + b * HSTRIDE + hofs + kc * 4);
                    aC0[b] = ffma2(wc0.x, h2.x, aC0[b]); aC0[b] = ffma2(wc0.y, h2.y, aC0[b]);
                    aC1[b] = ffma2(wc1.x, h2.x, aC1[b]); aC1[b] = ffma2(wc1.y, h2.y, aC1[b]);
                    aC2[b] = ffma2(wc2.x, h2.x, aC2[b]); aC2[b] = ffma2(wc2.y, h2.y, aC2[b]);
                    aC3[b] = ffma2(wc3.x, h2.x, aC3[b]); aC3[b] = ffma2(wc3.y, h2.y, aC3[b]);
                }
            }
#pragma unroll
            for (int b = 0; b < NBT; b++) {
                float s0 = hadd2(aC0[b]); s0 += __shfl_xor_sync(0xffffffffu, s0, 16);
                float s1 = hadd2(aC1[b]); s1 += __shfl_xor_sync(0xffffffffu, s1, 16);
                float s2 = hadd2(aC2[b]); s2 += __shfl_xor_sync(0xffffffffu, s2, 16);
                float s3 = hadd2(aC3[b]); s3 += __shfl_xor_sync(0xffffffffu, s3, 16);
                g1b_s[b * NGATE + rX] = half ? s2 : s0;
                g1b_s[b * NGATE + rY] = half ? s3 : s1;
            }
        }
        __syncthreads();   // A -> B

        // ---- act: act1(t) + act0(t+1) ----
        {
            float xv0 = __ldg(xr0 + t + 1);
            if (NBT == 7) {
                if (u1L0) {                   // tid < 64: L0, L0(b6), L1
                    float xv1 = __ldg(xr1 + t + 1);
                    actL0(gi0, hs0, cu0, xv0);
                    actL0(gi1, hs1, cu1, xv1);
                    actL1(gi2, hs2, cu2);
                } else if (hasU2) {           // 64..127: L0, L1, L1
                    actL0(gi0, hs0, cu0, xv0);
                    actL1(gi1, hs1, cu1);
                    actL1(gi2, hs2, cu2);
                } else {                      // 128..383: L0, L1
                    actL0(gi0, hs0, cu0, xv0);
                    actL1(gi1, hs1, cu1);
                }
            } else {                          // NBT == 6: L0, L1
                actL0(gi0, hs0, cu0, xv0);
                actL1(gi1, hs1, cu1);
            }
        }
        __syncthreads();   // B -> A
    }

    // ======== epilogue: mv1(511) + act1(511) ========
    if (isA) {
        u64 aB0[NBT], aB1[NBT];
#pragma unroll
        for (int b = 0; b < NBT; b++) { aB0[b] = 0ull; aB1[b] = 0ull; }
#pragma unroll
        for (int kc = 0; kc < 8; kc++) {
            ulonglong2 wb0 = wq[4096 + kc * 256 + wofsA];
            ulonglong2 wb1 = wq[6144 + kc * 256 + wofsA];
#pragma unroll
            for (int b = 0; b < NBT; b++) {
                ulonglong2 h2 = *(const ulonglong2*)(h0_s + b * HSTRIDE + hofs + kc * 4);
                aB0[b] = ffma2(wb0.x, h2.x, aB0[b]); aB0[b] = ffma2(wb0.y, h2.y, aB0[b]);
                aB1[b] = ffma2(wb1.x, h2.x, aB1[b]); aB1[b] = ffma2(wb1.y, h2.y, aB1[b]);
            }
        }
#pragma unroll
        for (int b = 0; b < NBT; b++) {
            float sB0 = hadd2(aB0[b]); sB0 += __shfl_xor_sync(0xffffffffu, sB0, 16);
            float sB1 = hadd2(aB1[b]); sB1 += __shfl_xor_sync(0xffffffffu, sB1, 16);
            g1a_s[b * NGATE + myrow] = (half ? sB1 : sB0) + b1v;
        }
    } else {
        u64 aC0[NBT], aC1[NBT], aC2[NBT], aC3[NBT];
#pragma unroll
        for (int b = 0; b < NBT; b++) { aC0[b]=0ull; aC1[b]=0ull; aC2[b]=0ull; aC3[b]=0ull; }
#pragma unroll
        for (int kc = 0; kc < 8; kc++) {
            ulonglong2 wc0 = wq[8192        + kc * 128 + wofsC];
            ulonglong2 wc1 = wq[8192 + 1024 + kc * 128 + wofsC];
            ulonglong2 wc2 = wq[8192 + 2048 + kc * 128 + wofsC];
            ulonglong2 wc3 = wq[8192 + 3072 + kc * 128 + wofsC];
#pragma unroll
            for (int b = 0; b < NBT; b++) {
                ulonglong2 h2 = *(const ulonglong2*)(h1_s + b * HSTRIDE + hofs + kc * 4);
                aC0[b] = ffma2(wc0.x, h2.x, aC0[b]); aC0[b] = ffma2(wc0.y, h2.y, aC0[b]);
                aC1[b] = ffma2(wc1.x, h2.x, aC1[b]); aC1[b] = ffma2(wc1.y, h2.y, aC1[b]);
                aC2[b] = ffma2(wc2.x, h2.x, aC2[b]); aC2[b] = ffma2(wc2.y, h2.y, aC2[b]);
                aC3[b] = ffma2(wc3.x, h2.x, aC3[b]); aC3[b] = ffma2(wc3.y, h2.y, aC3[b]);
            }
        }
#pragma unroll
        for (int b = 0; b < NBT; b++) {
            float s0 = hadd2(aC0[b]); s0 += __shfl_xor_sync(0xffffffffu, s0, 16);
            float s1 = hadd2(aC1[b]); s1 += __shfl_xor_sync(0xffffffffu, s1, 16);
            float s2 = hadd2(aC2[b]); s2 += __shfl_xor_sync(0xffffffffu, s2, 16);
            float s3 = hadd2(aC3[b]); s3 += __shfl_xor_sync(0xffffffffu, s3, 16);
            g1b_s[b * NGATE + rX] = half ? s2 : s0;
            g1b_s[b * NGATE + rY] = half ? s3 : s1;
        }
    }
    __syncthreads();
    {   // act1(511): all L1 units
        if (NBT == 7) {
            if (!u1L0)  actL1(gi1, hs1, cu1);
            if (hasU2)  actL1(gi2, hs2, cu2);
        } else {
            actL1(gi1, hs1, cu1);
        }
    }
    __syncthreads();

    // ---- output FC ----
    if (tid < 2 * NBT) {
        int b = (tid < NBT) ? tid : tid - NBT;
        const float* hp = (tid < NBT) ? h0_s : h1_s;
        float s = b_fc[0];
#pragma unroll
        for (int uu = 0; uu < 64; uu++)
            s = fmaf(hp[b * HSTRIDE + uu + ((uu >> 5) << 2)], wfc_s[uu], s);
        out[(tid < NBT ? 0 : B_TOTAL) + bbase + b] = s;
    }
}

__global__ void __launch_bounds__(NTHREADS, 1)
lstm2_kernel(const float* __restrict__ x,
             const float* __restrict__ W_ih0, const float* __restrict__ W_hh0,
             const float* __restrict__ b_ih0, const float* __restrict__ b_hh0,
             const float* __restrict__ W_ih1, const float* __restrict__ W_hh1,
             const float* __restrict__ b_ih1, const float* __restrict__ b_hh1,
             const float* __restrict__ W_fc,  const float* __restrict__ b_fc,
             float* __restrict__ out)
{
    extern __shared__ char smem[];
    ulonglong2* wq = (ulonglong2*)(smem + SM_W);
    float* g0_s  = (float*)(smem + SM_G0);
    float* g1a_s = (float*)(smem + SM_G1A);
    float* g1b_s = (float*)(smem + SM_G1B);
    float* h0_s  = (float*)(smem + SM_H0);
    float* h1_s  = (float*)(smem + SM_H1);
    float* wfc_s = (float*)(smem + SM_WFC);

    const int tid = threadIdx.x;

    // ---- upload weights into conflict-free quad layouts (NB-independent) ----
    for (int idx = tid; idx < 4096; idx += NTHREADS) {
        int row = idx >> 4, q = idx & 15;
        int hh = q >> 3, kc = q & 7;
        int dA = (row >> 7) * 2048 + kc * 256 + hh * 128 + (row & 127);
        wq[dA]        = ((const ulonglong2*)W_hh0)[idx];
        wq[4096 + dA] = ((const ulonglong2*)W_ih1)[idx];
        int dC = 8192 + (row >> 6) * 1024 + kc * 128 + hh * 64 + (row & 63);
        wq[dC] = ((const ulonglong2*)W_hh1)[idx];
    }
    if (tid < 64) wfc_s[tid] = W_fc[tid];

    if (blockIdx.x < NCTA7) {
        lstm_body<7>(blockIdx.x * 7, x, W_ih0, b_ih0, b_hh0, b_ih1, b_hh1,
                     b_fc, out, wq, g0_s, g1a_s, g1b_s, h0_s, h1_s, wfc_s);
    } else {
        lstm_body<6>(NCTA7 * 7 + (blockIdx.x - NCTA7) * 6, x, W_ih0, b_ih0, b_hh0,
                     b_ih1, b_hh1, b_fc, out, wq, g0_s, g1a_s, g1b_s, h0_s, h1_s, wfc_s);
    }
}

extern "C" void kernel_launch(void* const* d_in, const int* in_sizes, int n_in,
                              void* d_out, int out_size) {
    const float* x     = (const float*)d_in[0];
    const float* W_ih0 = (const float*)d_in[1];
    const float* W_hh0 = (const float*)d_in[2];
    const float* b_ih0 = (const float*)d_in[3];
    const float* b_hh0 = (const float*)d_in[4];
    const float* W_ih1 = (const float*)d_in[5];
    const float* W_hh1 = (const float*)d_in[6];
    const float* b_ih1 = (const float*)d_in[7];
    const float* b_hh1 = (const float*)d_in[8];
    const float* W_fc  = (const float*)d_in[9];
    const float* b_fc  = (const float*)d_in[10];
    float* out = (float*)d_out;

    cudaFuncSetAttribute(lstm2_kernel,
                         cudaFuncAttributeMaxDynamicSharedMemorySize, SMEM_BYTES);
    lstm2_kernel<<<NCTA, NTHREADS, SMEM_BYTES>>>(
        x, W_ih0, W_hh0, b_ih0, b_hh0,
        W_ih1, W_hh1, b_ih1, b_hh1, W_fc, b_fc, out);
}

// round 11
// speedup vs baseline: 1.2726x; 1.1045x over previous
#include <cuda_runtime.h>

#define B_TOTAL   1024
#define T_STEPS   512
#define NGATE     256
#define NCTA      148
#define NCTA7     136      /* 136 CTAs * 7 + 12 CTAs * 6 = 1024 */
#define NTHREADS  384
#define HSTRIDE   68

typedef unsigned long long u64;

__device__ __forceinline__ u64 ffma2(u64 a, u64 b, u64 c) {
    u64 d;
    asm("fma.rn.f32x2 %0, %1, %2, %3;" : "=l"(d) : "l"(a), "l"(b), "l"(c));
    return d;
}
__device__ __forceinline__ float hadd2(u64 v) {
    float lo, hi;
    asm("mov.b64 {%0, %1}, %2;" : "=f"(lo), "=f"(hi) : "l"(v));
    return lo + hi;
}
__device__ __forceinline__ float tanh_apx(float x) {
    float y;
    asm("tanh.approx.f32 %0, %1;" : "=f"(y) : "f"(x));
    return y;
}
__device__ __forceinline__ float sig_apx(float x) {
    return fmaf(0.5f, tanh_apx(0.5f * x), 0.5f);
}

#define BAR_SYNC(id, cnt)   asm volatile("bar.sync %0, %1;"   :: "r"(id), "r"(cnt) : "memory")
#define BAR_ARRIVE(id, cnt) asm volatile("bar.arrive %0, %1;" :: "r"(id), "r"(cnt) : "memory")
// barrier ids: 0 = __syncthreads, 1/2 = FULL[slot], 3/4 = EMPTY[slot],
//              5 = alpha-internal (256), 6 = beta-internal (128)

// SMEM (bytes), sized for NB=7:
//  wq    [0, 196608): quads. A=whh0 [0,4096), B=wih1 [4096,8192), C=whh1 [8192,12288)
//        A/B sublayout: [rowhi][kc][half][row&127]   conflict-free
//        C   sublayout: [row>>6][kc][half][row&63]   conflict-free
//  g0    [196608): f32 [7 b][256 g]
//  g1a   [203776): f32 ring, 2 slots x [7 b][256 g]  (alpha partial + b1)
//  g1b   [218112): f32 [7 b][256 g]                  (beta partial)
//  h0    [225280): f32 [7 b][68]   half0 @ +0, half1 @ +36 floats
//  h1    [227200)
//  wfc   [229120): f32 [64]
#define SM_W      0
#define SM_G0     196608
#define SM_G1A    203776
#define SM_G1B    218112
#define SM_H0     225280
#define SM_H1     227200
#define SM_WFC    229120
#define SMEM_BYTES 229376
#define G1A_SLOT  1792     /* floats per ring slot */

template<int NBT>
__device__ __forceinline__ void lstm_body(
    int bbase, const float* __restrict__ x,
    const float* __restrict__ W_ih0,
    const float* __restrict__ b_ih0, const float* __restrict__ b_hh0,
    const float* __restrict__ b_ih1, const float* __restrict__ b_hh1,
    const float* __restrict__ b_fc, float* __restrict__ out,
    ulonglong2* wq, float* g0_s, float* g1a_s, float* g1b_s,
    float* h0_s, float* h1_s, float* wfc_s)
{
    const int tid  = threadIdx.x;
    const int lane = tid & 31;
    const int half = lane >> 4;
    const int hofs = half * 36;
    const int wid  = tid >> 5;

    for (int i = tid; i < NBT * HSTRIDE; i += NTHREADS) { h0_s[i] = 0.0f; h1_s[i] = 0.0f; }
    __syncthreads();   // weights + zeros visible to all

    if (tid < 256) {
        // ================= ALPHA: whh0 + wih1 on h0 ; act0 =================
        const int sl    = (wid & 7) * 16 + (lane & 15);
        const int wofsA = half * 128 + sl;
        const int myrow = sl + half * 128;
        const float b0v = b_ih0[myrow] + b_hh0[myrow];
        const float b1v = b_ih1[myrow] + b_hh1[myrow];

        const int uA  = tid & 63;
        const int bA0 = tid >> 6;                 // 0..3
        const int bA1 = 4 + bA0;
        const bool hasA1 = (tid < (NBT - 4) * 64);
        const int pad = (uA >> 5) << 2;
        const int gi0 = bA0 * NGATE + uA, hs0 = bA0 * HSTRIDE + uA + pad;
        const int gi1 = bA1 * NGATE + uA, hs1 = bA1 * HSTRIDE + uA + pad;
        const float* xr0 = x + (size_t)(bbase + bA0) * T_STEPS;
        const float* xr1 = x + (size_t)(bbase + bA1) * T_STEPS;
        const float wxi = W_ih0[uA];
        const float wxf = W_ih0[64 + uA];
        const float wxg = W_ih0[128 + uA];
        const float wxo = W_ih0[192 + uA];
        float cA0 = 0.0f, cA1 = 0.0f;

        auto actL0 = [&](int gi, int hs, float& c, float xv) {
            float q0 = fmaf(wxi, xv, g0_s[gi]);
            float q1 = fmaf(wxf, xv, g0_s[gi + 64]);
            float q2 = fmaf(wxg, xv, g0_s[gi + 128]);
            float q3 = fmaf(wxo, xv, g0_s[gi + 192]);
            float ii = sig_apx(q0), ff = sig_apx(q1), gv = tanh_apx(q2), oo = sig_apx(q3);
            c = ff * c + ii * gv;
            h0_s[hs] = oo * tanh_apx(c);
        };

        // prologue: g0(0) = b0 ; act0(0)
#pragma unroll
        for (int b = 0; b < NBT; b++) g0_s[b * NGATE + myrow] = b0v;
        BAR_SYNC(5, 256);
        actL0(gi0, hs0, cA0, __ldg(xr0));
        if (hasA1) actL0(gi1, hs1, cA1, __ldg(xr1));
        BAR_SYNC(5, 256);

        for (int t = 0; t < T_STEPS; t++) {
            if (t >= 2) BAR_SYNC(3 + (t & 1), 384);      // EMPTY: slot reusable
            float* g1a = g1a_s + (t & 1) * G1A_SLOT;

            u64 aA0[NBT], aA1[NBT], aB0[NBT], aB1[NBT];
#pragma unroll
            for (int b = 0; b < NBT; b++) { aA0[b]=0ull; aA1[b]=0ull; aB0[b]=0ull; aB1[b]=0ull; }
#pragma unroll
            for (int kc = 0; kc < 8; kc++) {
                ulonglong2 wa0 = wq[       kc * 256 + wofsA];
                ulonglong2 wa1 = wq[2048 + kc * 256 + wofsA];
                ulonglong2 wb0 = wq[4096 + kc * 256 + wofsA];
                ulonglong2 wb1 = wq[6144 + kc * 256 + wofsA];
#pragma unroll
                for (int b = 0; b < NBT; b++) {
                    ulonglong2 h2 = *(const ulonglong2*)(h0_s + b * HSTRIDE + hofs + kc * 4);
                    aA0[b] = ffma2(wa0.x, h2.x, aA0[b]); aA0[b] = ffma2(wa0.y, h2.y, aA0[b]);
                    aA1[b] = ffma2(wa1.x, h2.x, aA1[b]); aA1[b] = ffma2(wa1.y, h2.y, aA1[b]);
                    aB0[b] = ffma2(wb0.x, h2.x, aB0[b]); aB0[b] = ffma2(wb0.y, h2.y, aB0[b]);
                    aB1[b] = ffma2(wb1.x, h2.x, aB1[b]); aB1[b] = ffma2(wb1.y, h2.y, aB1[b]);
                }
            }
#pragma unroll
            for (int b = 0; b < NBT; b++) {
                float sA0 = hadd2(aA0[b]); sA0 += __shfl_xor_sync(0xffffffffu, sA0, 16);
                float sA1 = hadd2(aA1[b]); sA1 += __shfl_xor_sync(0xffffffffu, sA1, 16);
                float sB0 = hadd2(aB0[b]); sB0 += __shfl_xor_sync(0xffffffffu, sB0, 16);
                float sB1 = hadd2(aB1[b]); sB1 += __shfl_xor_sync(0xffffffffu, sB1, 16);
                g0_s[b * NGATE + myrow] = (half ? sA1 : sA0) + b0v;   // g0(t+1)
                g1a [b * NGATE + myrow] = (half ? sB1 : sB0) + b1v;   // g1a(t)
            }
            BAR_SYNC(5, 256);                 // drain stores (alpha-wide)
            BAR_ARRIVE(1 + (t & 1), 384);     // FULL: g1a(t) published to beta

            if (t < T_STEPS - 1) {            // act0(t+1)
                float xv0 = __ldg(xr0 + t + 1);
                actL0(gi0, hs0, cA0, xv0);
                if (hasA1) {
                    float xv1 = __ldg(xr1 + t + 1);
                    actL0(gi1, hs1, cA1, xv1);
                }
            }
            BAR_SYNC(5, 256);                 // h0(t+1) visible for next mv
        }
    } else {
        // ================= BETA: whh1 on h1 ; act1 =================
        const int sb    = (wid - 8) * 16 + (lane & 15);
        const int wofsC = half * 64 + sb;
        const int rX    = sb + 64 * (half * 2);
        const int rY    = rX + 64;

        const int btid = tid - 256;
        const int uB   = btid & 63;
        const int pad  = (uB >> 5) << 2;
        const int bB   = btid >> 6;           // 0 or 1
        float cB0 = 0.0f, cB1 = 0.0f, cB2 = 0.0f, cB3 = 0.0f;
        const bool hasJ3 = (NBT == 7) && (btid < 64);

        auto actL1 = [&](const float* g1a, int b, float& c) {
            int gi = b * NGATE + uB;
            float p0 = g1a[gi]       + g1b_s[gi];
            float p1 = g1a[gi + 64]  + g1b_s[gi + 64];
            float p2 = g1a[gi + 128] + g1b_s[gi + 128];
            float p3 = g1a[gi + 192] + g1b_s[gi + 192];
            float ii = sig_apx(p0), ff = sig_apx(p1), gv = tanh_apx(p2), oo = sig_apx(p3);
            c = ff * c + ii * gv;
            h1_s[b * HSTRIDE + uB + pad] = oo * tanh_apx(c);
        };

        for (int t = 0; t < T_STEPS; t++) {
            u64 aC0[NBT], aC1[NBT], aC2[NBT], aC3[NBT];
#pragma unroll
            for (int b = 0; b < NBT; b++) { aC0[b]=0ull; aC1[b]=0ull; aC2[b]=0ull; aC3[b]=0ull; }
#pragma unroll
            for (int kc = 0; kc < 8; kc++) {
                ulonglong2 wc0 = wq[8192        + kc * 128 + wofsC];
                ulonglong2 wc1 = wq[8192 + 1024 + kc * 128 + wofsC];
                ulonglong2 wc2 = wq[8192 + 2048 + kc * 128 + wofsC];
                ulonglong2 wc3 = wq[8192 + 3072 + kc * 128 + wofsC];
#pragma unroll
                for (int b = 0; b < NBT; b++) {
                    ulonglong2 h2 = *(const ulonglong2*)(h1_s + b * HSTRIDE + hofs + kc * 4);
                    aC0[b] = ffma2(wc0.x, h2.x, aC0[b]); aC0[b] = ffma2(wc0.y, h2.y, aC0[b]);
                    aC1[b] = ffma2(wc1.x, h2.x, aC1[b]); aC1[b] = ffma2(wc1.y, h2.y, aC1[b]);
                    aC2[b] = ffma2(wc2.x, h2.x, aC2[b]); aC2[b] = ffma2(wc2.y, h2.y, aC2[b]);
                    aC3[b] = ffma2(wc3.x, h2.x, aC3[b]); aC3[b] = ffma2(wc3.y, h2.y, aC3[b]);
                }
            }
#pragma unroll
            for (int b = 0; b < NBT; b++) {
                float s0 = hadd2(aC0[b]); s0 += __shfl_xor_sync(0xffffffffu, s0, 16);
                float s1 = hadd2(aC1[b]); s1 += __shfl_xor_sync(0xffffffffu, s1, 16);
                float s2 = hadd2(aC2[b]); s2 += __shfl_xor_sync(0xffffffffu, s2, 16);
                float s3 = hadd2(aC3[b]); s3 += __shfl_xor_sync(0xffffffffu, s3, 16);
                g1b_s[b * NGATE + rX] = half ? s2 : s0;
                g1b_s[b * NGATE + rY] = half ? s3 : s1;
            }
            BAR_SYNC(6, 128);                 // g1b drained (beta-wide)
            BAR_SYNC(1 + (t & 1), 384);       // FULL: wait g1a(t) from alpha
            const float* g1a = g1a_s + (t & 1) * G1A_SLOT;

            actL1(g1a, bB,     cB0);          // act1(t)
            actL1(g1a, bB + 2, cB1);
            actL1(g1a, bB + 4, cB2);
            if (hasJ3) actL1(g1a, bB + 6, cB3);

            BAR_ARRIVE(3 + (t & 1), 384);     // EMPTY: g1a slot consumed
            BAR_SYNC(6, 128);                 // h1(t) visible for next mv
        }
    }
    __syncthreads();

    // ---- output FC ----
    if (tid < 2 * NBT) {
        int b = (tid < NBT) ? tid : tid - NBT;
        const float* hp = (tid < NBT) ? h0_s : h1_s;
        float s = b_fc[0];
#pragma unroll
        for (int uu = 0; uu < 64; uu++)
            s = fmaf(hp[b * HSTRIDE + uu + ((uu >> 5) << 2)], wfc_s[uu], s);
        out[(tid < NBT ? 0 : B_TOTAL) + bbase + b] = s;
    }
}

__global__ void __launch_bounds__(NTHREADS, 1)
lstm2_kernel(const float* __restrict__ x,
             const float* __restrict__ W_ih0, const float* __restrict__ W_hh0,
             const float* __restrict__ b_ih0, const float* __restrict__ b_hh0,
             const float* __restrict__ W_ih1, const float* __restrict__ W_hh1,
             const float* __restrict__ b_ih1, const float* __restrict__ b_hh1,
             const float* __restrict__ W_fc,  const float* __restrict__ b_fc,
             float* __restrict__ out)
{
    extern __shared__ char smem[];
    ulonglong2* wq = (ulonglong2*)(smem + SM_W);
    float* g0_s  = (float*)(smem + SM_G0);
    float* g1a_s = (float*)(smem + SM_G1A);
    float* g1b_s = (float*)(smem + SM_G1B);
    float* h0_s  = (float*)(smem + SM_H0);
    float* h1_s  = (float*)(smem + SM_H1);
    float* wfc_s = (float*)(smem + SM_WFC);

    const int tid = threadIdx.x;

    // ---- upload weights into conflict-free quad layouts ----
    for (int idx = tid; idx < 4096; idx += NTHREADS) {
        int row = idx >> 4, q = idx & 15;
        int hh = q >> 3, kc = q & 7;
        int dA = (row >> 7) * 2048 + kc * 256 + hh * 128 + (row & 127);
        wq[dA]        = ((const ulonglong2*)W_hh0)[idx];
        wq[4096 + dA] = ((const ulonglong2*)W_ih1)[idx];
        int dC = 8192 + (row >> 6) * 1024 + kc * 128 + hh * 64 + (row & 63);
        wq[dC] = ((const ulonglong2*)W_hh1)[idx];
    }
    if (tid < 64) wfc_s[tid] = W_fc[tid];

    if (blockIdx.x < NCTA7) {
        lstm_body<7>(blockIdx.x * 7, x, W_ih0, b_ih0, b_hh0, b_ih1, b_hh1,
                     b_fc, out, wq, g0_s, g1a_s, g1b_s, h0_s, h1_s, wfc_s);
    } else {
        lstm_body<6>(NCTA7 * 7 + (blockIdx.x - NCTA7) * 6, x, W_ih0, b_ih0, b_hh0,
                     b_ih1, b_hh1, b_fc, out, wq, g0_s, g1a_s, g1b_s, h0_s, h1_s, wfc_s);
    }
}

extern "C" void kernel_launch(void* const* d_in, const int* in_sizes, int n_in,
                              void* d_out, int out_size) {
    const float* x     = (const float*)d_in[0];
    const float* W_ih0 = (const float*)d_in[1];
    const float* W_hh0 = (const float*)d_in[2];
    const float* b_ih0 = (const float*)d_in[3];
    const float* b_hh0 = (const float*)d_in[4];
    const float* W_ih1 = (const float*)d_in[5];
    const float* W_hh1 = (const float*)d_in[6];
    const float* b_ih1 = (const float*)d_in[7];
    const float* b_hh1 = (const float*)d_in[8];
    const float* W_fc  = (const float*)d_in[9];
    const float* b_fc  = (const float*)d_in[10];
    float* out = (float*)d_out;

    cudaFuncSetAttribute(lstm2_kernel,
                         cudaFuncAttributeMaxDynamicSharedMemorySize, SMEM_BYTES);
    lstm2_kernel<<<NCTA, NTHREADS, SMEM_BYTES>>>(
        x, W_ih0, W_hh0, b_ih0, b_hh0,
        W_ih1, W_hh1, b_ih1, b_hh1, W_fc, b_fc, out);
}